// round 9
// baseline (speedup 1.0000x reference)
#include <cuda_runtime.h>

#define TT 12
#define SS 16
#define NT 256   // threads per block = rows per block
#define YS 19    // y row stride: 16 species + sentinel1(=1.0) + sentinel0(=0.0); odd
#define FS 25    // combined rate row: 12 fwd + 12 rev + pad; odd -> conflict-free

struct Params {
    ulonglong2 eff2[TT][4]; // effects row as 4x (2x packed f32x2) = 16 floats
    int4 idx[TT];           // x=sub, y=prod(17 if irreversible), z=fr, w=to
};

// Read by mech_kernel via the uniform/constant port (LDCU). Its backing store
// in global memory is written directly by prep_kernel through the symbol
// address; the constant cache is cold at each launch, so reads are fresh.
__constant__ Params c_p;

// Robustly decode one element of a boolean array whose on-device dtype may be
// int32, uint8/bool, or float32. Detection reads only the first 12 bytes.
__device__ __forceinline__ int decode_bool_elem(const unsigned char* p, int i) {
    bool is_f32 = false;                       // float32 1.0f = [00 00 80 3F]
    #pragma unroll
    for (int k = 0; k < 3; k++)
        if (p[4 * k + 2] == 0x80 && p[4 * k + 3] == 0x3F) is_f32 = true;
    if (is_f32) return (((const float*)p)[i] != 0.0f) ? 1 : 0;
    bool off_nonzero = false;                  // uint8: nonzero at off-word bytes
    #pragma unroll
    for (int j = 0; j < 12; j++)
        if ((j & 3) && p[j]) off_nonzero = true;
    if (off_nonzero) return (p[i] != 0) ? 1 : 0;
    return (((const int*)p)[i] != 0) ? 1 : 0;  // int32
}

__global__ void prep_kernel(Params* __restrict__ pc,
                            const float* __restrict__ stoich,
                            const float* __restrict__ effects,
                            const int* __restrict__ from_idx,
                            const unsigned char* __restrict__ from_valid,
                            const int* __restrict__ to_idx,
                            const unsigned char* __restrict__ to_valid,
                            const unsigned char* __restrict__ reversible)
{
    const int t = threadIdx.x;
    if (t >= TT) return;

    int sub = -1, prod = -1;
    #pragma unroll
    for (int s = 0; s < SS; s++) {
        float v = stoich[t * SS + s];
        if (v < -0.5f) sub = s;
        if (v >  0.5f) prod = s;
    }
    int4 ix;
    ix.x = (sub  >= 0) ? sub  : 16;                   // gathers 1.0
    ix.y = (prod >= 0) ? prod : 16;
    if (!decode_bool_elem(reversible, t)) ix.y = 17;  // gathers 0.0 -> kills rev
    ix.z = decode_bool_elem(from_valid, t) ? from_idx[t] : 16;
    ix.w = decode_bool_elem(to_valid,  t)  ? to_idx[t]   : 16;
    pc->idx[t] = ix;

    #pragma unroll
    for (int j = 0; j < 4; j++) {
        unsigned long long pk0, pk1;
        asm("mov.b64 %0, {%1, %2};" : "=l"(pk0)
            : "f"(effects[t * SS + 4 * j]), "f"(effects[t * SS + 4 * j + 1]));
        asm("mov.b64 %0, {%1, %2};" : "=l"(pk1)
            : "f"(effects[t * SS + 4 * j + 2]), "f"(effects[t * SS + 4 * j + 3]));
        pc->eff2[t][j] = make_ulonglong2(pk0, pk1);
    }
}

__global__ void __launch_bounds__(NT, 5)
mech_kernel(const float4* __restrict__ y4,
            const float4* __restrict__ f4,
            const float4* __restrict__ r4,
            float4* __restrict__ out4,
            int B)
{
    __shared__ float ys[NT * YS];
    __shared__ float frs[NT * FS];   // per row: [0..11]=fwd, [12..23]=rev

    const int tid  = threadIdx.x;
    const int row0 = blockIdx.x * NT;
    const int nrow = min(NT, B - row0);
    const bool full = (nrow == NT);

    // ---- coalesced staging ----
    if (full) {
        #pragma unroll
        for (int k = 0; k < 4; k++) {           // y: NT*4 float4s
            int idx = tid + k * NT;
            float4 v = y4[(long)row0 * 4 + idx];
            int r = idx >> 2, p = (idx & 3) * 4;
            ys[r * YS + p + 0] = v.x; ys[r * YS + p + 1] = v.y;
            ys[r * YS + p + 2] = v.z; ys[r * YS + p + 3] = v.w;
        }
        #pragma unroll
        for (int k = 0; k < 3; k++) {           // f and r: NT*3 float4s each
            int idx = tid + k * NT;
            int r = idx / 3, p = (idx - r * 3) * 4;
            float4 a = f4[(long)row0 * 3 + idx];
            frs[r * FS + p + 0] = a.x; frs[r * FS + p + 1] = a.y;
            frs[r * FS + p + 2] = a.z; frs[r * FS + p + 3] = a.w;
            float4 c = r4[(long)row0 * 3 + idx];
            frs[r * FS + 12 + p + 0] = c.x; frs[r * FS + 12 + p + 1] = c.y;
            frs[r * FS + 12 + p + 2] = c.z; frs[r * FS + 12 + p + 3] = c.w;
        }
    } else {
        #pragma unroll
        for (int k = 0; k < 4; k++) {
            int idx = tid + k * NT;
            if (idx < nrow * 4) {
                float4 v = y4[(long)row0 * 4 + idx];
                int r = idx >> 2, p = (idx & 3) * 4;
                ys[r * YS + p + 0] = v.x; ys[r * YS + p + 1] = v.y;
                ys[r * YS + p + 2] = v.z; ys[r * YS + p + 3] = v.w;
            }
        }
        #pragma unroll
        for (int k = 0; k < 3; k++) {
            int idx = tid + k * NT;
            if (idx < nrow * 3) {
                int r = idx / 3, p = (idx - r * 3) * 4;
                float4 a = f4[(long)row0 * 3 + idx];
                frs[r * FS + p + 0] = a.x; frs[r * FS + p + 1] = a.y;
                frs[r * FS + p + 2] = a.z; frs[r * FS + p + 3] = a.w;
                float4 c = r4[(long)row0 * 3 + idx];
                frs[r * FS + 12 + p + 0] = c.x; frs[r * FS + 12 + p + 1] = c.y;
                frs[r * FS + 12 + p + 2] = c.z; frs[r * FS + 12 + p + 3] = c.w;
            }
        }
    }
    ys[tid * YS + 16] = 1.0f;                   // sentinel one
    ys[tid * YS + 17] = 0.0f;                   // sentinel zero (irreversible)
    __syncthreads();

    // ---- compute (params via uniform/constant port, payload via smem) ----
    if (tid < nrow) {
        const int yb = tid * YS;
        const int fb = tid * FS;

        unsigned long long acc2[8];
        #pragma unroll
        for (int j = 0; j < 8; j++) acc2[j] = 0ull;

        #pragma unroll
        for (int t = 0; t < TT; t++) {
            const int4 ci = c_p.idx[t];          // LDCU (uniform port)
            float sc = ys[yb + ci.x];
            float pc = ys[yb + ci.y];            // 0.0 if irreversible
            float ef = ys[yb + ci.z];
            float er = ys[yb + ci.w];
            float v  = frs[fb + t] * ef * sc - frs[fb + 12 + t] * er * pc;
            unsigned long long v2;
            asm("mov.b64 %0, {%1, %1};" : "=l"(v2) : "f"(v));
            #pragma unroll
            for (int j = 0; j < 4; j++) {
                ulonglong2 e = c_p.eff2[t][j];   // LDCU.128
                asm("fma.rn.f32x2 %0, %1, %2, %3;"
                    : "=l"(acc2[2 * j])     : "l"(v2), "l"(e.x), "l"(acc2[2 * j]));
                asm("fma.rn.f32x2 %0, %1, %2, %3;"
                    : "=l"(acc2[2 * j + 1]) : "l"(v2), "l"(e.y), "l"(acc2[2 * j + 1]));
            }
        }

        // park result in own ys row (this thread's gathers are done)
        #pragma unroll
        for (int j = 0; j < 8; j++) {
            float lo, hi;
            asm("mov.b64 {%0, %1}, %2;" : "=f"(lo), "=f"(hi) : "l"(acc2[j]));
            ys[yb + 2 * j]     = lo;
            ys[yb + 2 * j + 1] = hi;
        }
    }
    __syncthreads();

    // ---- coalesced store ----
    if (full) {
        #pragma unroll
        for (int k = 0; k < 4; k++) {
            int idx = tid + k * NT;
            int r = idx >> 2, p = (idx & 3) * 4;
            float4 o;
            o.x = ys[r * YS + p + 0]; o.y = ys[r * YS + p + 1];
            o.z = ys[r * YS + p + 2]; o.w = ys[r * YS + p + 3];
            out4[(long)row0 * 4 + idx] = o;
        }
    } else {
        #pragma unroll
        for (int k = 0; k < 4; k++) {
            int idx = tid + k * NT;
            if (idx < nrow * 4) {
                int r = idx >> 2, p = (idx & 3) * 4;
                float4 o;
                o.x = ys[r * YS + p + 0]; o.y = ys[r * YS + p + 1];
                o.z = ys[r * YS + p + 2]; o.w = ys[r * YS + p + 3];
                out4[(long)row0 * 4 + idx] = o;
            }
        }
    }
}

extern "C" void kernel_launch(void* const* d_in, const int* in_sizes, int n_in,
                              void* d_out, int out_size)
{
    // Input order: t, y, forward_rates, reverse_rates, stoich, effects,
    // from_idx, from_valid, to_idx, to_valid, reversible
    const float* y       = (const float*)d_in[1];
    const float* fr      = (const float*)d_in[2];
    const float* rr      = (const float*)d_in[3];
    const float* stoich  = (const float*)d_in[4];
    const float* effects = (const float*)d_in[5];
    const int*   from_i  = (const int*)d_in[6];
    const unsigned char* from_v = (const unsigned char*)d_in[7];
    const int*   to_i    = (const int*)d_in[8];
    const unsigned char* to_v   = (const unsigned char*)d_in[9];
    const unsigned char* rev    = (const unsigned char*)d_in[10];

    // prep writes straight into the constant symbol's global backing store —
    // no graph memcpy node needed.
    void* c_p_addr = nullptr;
    cudaGetSymbolAddress(&c_p_addr, c_p);
    prep_kernel<<<1, 32>>>((Params*)c_p_addr, stoich, effects,
                           from_i, from_v, to_i, to_v, rev);

    const int B = in_sizes[1] / SS;
    const int grid = (B + NT - 1) / NT;
    mech_kernel<<<grid, NT>>>((const float4*)y, (const float4*)fr,
                              (const float4*)rr, (float4*)d_out, B);
}

// round 10
// speedup vs baseline: 1.0209x; 1.0209x over previous
#include <cuda_runtime.h>

#define TT 12
#define SS 16
#define NT 256   // threads per block = rows per block
#define YS 19    // y row stride: 16 species + sentinel1(=1.0) + sentinel0(=0.0); odd
#define FS 25    // combined rate row: 12 fwd + 12 rev + pad; odd -> conflict-free

struct Params {
    ulonglong2 eff2[TT][4]; // effects row as 4x (2x packed f32x2) = 16 floats
    int4 idx[TT];           // x=sub, y=prod(17 if irreversible), z=fr, w=to
};

// Read by mech_kernel via the uniform/constant port (LDCU). Its backing store
// in global memory is written directly by prep_kernel through the symbol
// address; the constant cache is cold at each launch, so reads are fresh.
__constant__ Params c_p;

// Robustly decode one element of a boolean array whose on-device dtype may be
// int32, uint8/bool, or float32. Detection reads only the first 12 bytes.
__device__ __forceinline__ int decode_bool_elem(const unsigned char* p, int i) {
    bool is_f32 = false;                       // float32 1.0f = [00 00 80 3F]
    #pragma unroll
    for (int k = 0; k < 3; k++)
        if (p[4 * k + 2] == 0x80 && p[4 * k + 3] == 0x3F) is_f32 = true;
    if (is_f32) return (((const float*)p)[i] != 0.0f) ? 1 : 0;
    bool off_nonzero = false;                  // uint8: nonzero at off-word bytes
    #pragma unroll
    for (int j = 0; j < 12; j++)
        if ((j & 3) && p[j]) off_nonzero = true;
    if (off_nonzero) return (p[i] != 0) ? 1 : 0;
    return (((const int*)p)[i] != 0) ? 1 : 0;  // int32
}

__global__ void prep_kernel(Params* __restrict__ pc,
                            const float* __restrict__ stoich,
                            const float* __restrict__ effects,
                            const int* __restrict__ from_idx,
                            const unsigned char* __restrict__ from_valid,
                            const int* __restrict__ to_idx,
                            const unsigned char* __restrict__ to_valid,
                            const unsigned char* __restrict__ reversible)
{
    const int t = threadIdx.x;
    if (t >= TT) return;

    int sub = -1, prod = -1;
    #pragma unroll
    for (int s = 0; s < SS; s++) {
        float v = stoich[t * SS + s];
        if (v < -0.5f) sub = s;
        if (v >  0.5f) prod = s;
    }
    int4 ix;
    ix.x = (sub  >= 0) ? sub  : 16;                   // gathers 1.0
    ix.y = (prod >= 0) ? prod : 16;
    if (!decode_bool_elem(reversible, t)) ix.y = 17;  // gathers 0.0 -> kills rev
    ix.z = decode_bool_elem(from_valid, t) ? from_idx[t] : 16;
    ix.w = decode_bool_elem(to_valid,  t)  ? to_idx[t]   : 16;
    pc->idx[t] = ix;

    #pragma unroll
    for (int j = 0; j < 4; j++) {
        unsigned long long pk0, pk1;
        asm("mov.b64 %0, {%1, %2};" : "=l"(pk0)
            : "f"(effects[t * SS + 4 * j]), "f"(effects[t * SS + 4 * j + 1]));
        asm("mov.b64 %0, {%1, %2};" : "=l"(pk1)
            : "f"(effects[t * SS + 4 * j + 2]), "f"(effects[t * SS + 4 * j + 3]));
        pc->eff2[t][j] = make_ulonglong2(pk0, pk1);
    }
}

__global__ void __launch_bounds__(NT, 5)
mech_kernel(const float4* __restrict__ y4,
            const float4* __restrict__ f4,
            const float4* __restrict__ r4,
            float4* __restrict__ out4,
            int B)
{
    __shared__ float ys[NT * YS];
    __shared__ float frs[NT * FS];   // per row: [0..11]=fwd, [12..23]=rev

    const int tid  = threadIdx.x;
    const int row0 = blockIdx.x * NT;
    const int nrow = min(NT, B - row0);
    const bool full = (nrow == NT);

    // ---- coalesced staging ----
    if (full) {
        #pragma unroll
        for (int k = 0; k < 4; k++) {           // y: NT*4 float4s
            int idx = tid + k * NT;
            float4 v = y4[(long)row0 * 4 + idx];
            int r = idx >> 2, p = (idx & 3) * 4;
            ys[r * YS + p + 0] = v.x; ys[r * YS + p + 1] = v.y;
            ys[r * YS + p + 2] = v.z; ys[r * YS + p + 3] = v.w;
        }
        #pragma unroll
        for (int k = 0; k < 3; k++) {           // f and r: NT*3 float4s each
            int idx = tid + k * NT;
            int r = idx / 3, p = (idx - r * 3) * 4;
            float4 a = f4[(long)row0 * 3 + idx];
            frs[r * FS + p + 0] = a.x; frs[r * FS + p + 1] = a.y;
            frs[r * FS + p + 2] = a.z; frs[r * FS + p + 3] = a.w;
            float4 c = r4[(long)row0 * 3 + idx];
            frs[r * FS + 12 + p + 0] = c.x; frs[r * FS + 12 + p + 1] = c.y;
            frs[r * FS + 12 + p + 2] = c.z; frs[r * FS + 12 + p + 3] = c.w;
        }
    } else {
        #pragma unroll
        for (int k = 0; k < 4; k++) {
            int idx = tid + k * NT;
            if (idx < nrow * 4) {
                float4 v = y4[(long)row0 * 4 + idx];
                int r = idx >> 2, p = (idx & 3) * 4;
                ys[r * YS + p + 0] = v.x; ys[r * YS + p + 1] = v.y;
                ys[r * YS + p + 2] = v.z; ys[r * YS + p + 3] = v.w;
            }
        }
        #pragma unroll
        for (int k = 0; k < 3; k++) {
            int idx = tid + k * NT;
            if (idx < nrow * 3) {
                int r = idx / 3, p = (idx - r * 3) * 4;
                float4 a = f4[(long)row0 * 3 + idx];
                frs[r * FS + p + 0] = a.x; frs[r * FS + p + 1] = a.y;
                frs[r * FS + p + 2] = a.z; frs[r * FS + p + 3] = a.w;
                float4 c = r4[(long)row0 * 3 + idx];
                frs[r * FS + 12 + p + 0] = c.x; frs[r * FS + 12 + p + 1] = c.y;
                frs[r * FS + 12 + p + 2] = c.z; frs[r * FS + 12 + p + 3] = c.w;
            }
        }
    }
    ys[tid * YS + 16] = 1.0f;                   // sentinel one
    ys[tid * YS + 17] = 0.0f;                   // sentinel zero (irreversible)
    __syncthreads();

    // ---- compute (params via uniform/constant port, payload via smem) ----
    if (tid < nrow) {
        const int yb = tid * YS;
        const int fb = tid * FS;

        unsigned long long acc2[8];
        #pragma unroll
        for (int j = 0; j < 8; j++) acc2[j] = 0ull;

        #pragma unroll
        for (int t = 0; t < TT; t++) {
            const int4 ci = c_p.idx[t];          // LDCU (uniform port)
            float sc = ys[yb + ci.x];
            float pc = ys[yb + ci.y];            // 0.0 if irreversible
            float ef = ys[yb + ci.z];
            float er = ys[yb + ci.w];
            float v  = frs[fb + t] * ef * sc - frs[fb + 12 + t] * er * pc;
            unsigned long long v2;
            asm("mov.b64 %0, {%1, %1};" : "=l"(v2) : "f"(v));
            #pragma unroll
            for (int j = 0; j < 4; j++) {
                ulonglong2 e = c_p.eff2[t][j];   // LDCU.128
                asm("fma.rn.f32x2 %0, %1, %2, %3;"
                    : "=l"(acc2[2 * j])     : "l"(v2), "l"(e.x), "l"(acc2[2 * j]));
                asm("fma.rn.f32x2 %0, %1, %2, %3;"
                    : "=l"(acc2[2 * j + 1]) : "l"(v2), "l"(e.y), "l"(acc2[2 * j + 1]));
            }
        }

        // park result in own ys row (this thread's gathers are done)
        #pragma unroll
        for (int j = 0; j < 8; j++) {
            float lo, hi;
            asm("mov.b64 {%0, %1}, %2;" : "=f"(lo), "=f"(hi) : "l"(acc2[j]));
            ys[yb + 2 * j]     = lo;
            ys[yb + 2 * j + 1] = hi;
        }
    }
    __syncthreads();

    // ---- coalesced store ----
    if (full) {
        #pragma unroll
        for (int k = 0; k < 4; k++) {
            int idx = tid + k * NT;
            int r = idx >> 2, p = (idx & 3) * 4;
            float4 o;
            o.x = ys[r * YS + p + 0]; o.y = ys[r * YS + p + 1];
            o.z = ys[r * YS + p + 2]; o.w = ys[r * YS + p + 3];
            out4[(long)row0 * 4 + idx] = o;
        }
    } else {
        #pragma unroll
        for (int k = 0; k < 4; k++) {
            int idx = tid + k * NT;
            if (idx < nrow * 4) {
                int r = idx >> 2, p = (idx & 3) * 4;
                float4 o;
                o.x = ys[r * YS + p + 0]; o.y = ys[r * YS + p + 1];
                o.z = ys[r * YS + p + 2]; o.w = ys[r * YS + p + 3];
                out4[(long)row0 * 4 + idx] = o;
            }
        }
    }
}

extern "C" void kernel_launch(void* const* d_in, const int* in_sizes, int n_in,
                              void* d_out, int out_size)
{
    // Input order: t, y, forward_rates, reverse_rates, stoich, effects,
    // from_idx, from_valid, to_idx, to_valid, reversible
    const float* y       = (const float*)d_in[1];
    const float* fr      = (const float*)d_in[2];
    const float* rr      = (const float*)d_in[3];
    const float* stoich  = (const float*)d_in[4];
    const float* effects = (const float*)d_in[5];
    const int*   from_i  = (const int*)d_in[6];
    const unsigned char* from_v = (const unsigned char*)d_in[7];
    const int*   to_i    = (const int*)d_in[8];
    const unsigned char* to_v   = (const unsigned char*)d_in[9];
    const unsigned char* rev    = (const unsigned char*)d_in[10];

    // prep writes straight into the constant symbol's global backing store —
    // no graph memcpy node needed.
    void* c_p_addr = nullptr;
    cudaGetSymbolAddress(&c_p_addr, c_p);
    prep_kernel<<<1, 32>>>((Params*)c_p_addr, stoich, effects,
                           from_i, from_v, to_i, to_v, rev);

    const int B = in_sizes[1] / SS;
    const int grid = (B + NT - 1) / NT;
    mech_kernel<<<grid, NT>>>((const float4*)y, (const float4*)fr,
                              (const float4*)rr, (float4*)d_out, B);
}